// round 12
// baseline (speedup 1.0000x reference)
#include <cuda_runtime.h>
#include <cuda_fp16.h>
#include <cstdint>

#define DIM 128
#define NTH 256
#define WARPS 8
#define ROWS_PER_WARP 32
#define PI_F 3.14159265358979323846f

// ---- smem: two 128x128 fp16 weight tiles (swizzled) + biases ----
#define OFF_W1  0
#define OFF_W2  32768
#define OFF_B1  65536
#define OFF_B2  66048
#define SMEM_TOTAL 66560

__device__ __forceinline__ uint32_t swz(int row, int kElem) {
    return (uint32_t)(row * 256) + (((uint32_t)(kElem * 2)) ^ (uint32_t)((row & 7) << 4));
}

__device__ __forceinline__ uint32_t smem_u32(const void* p) {
    uint32_t a;
    asm("{ .reg .u64 t; cvta.to.shared.u64 t, %1; cvt.u32.u64 %0, t; }" : "=r"(a) : "l"(p));
    return a;
}

__device__ __forceinline__ void ldsm4(uint32_t& r0, uint32_t& r1, uint32_t& r2, uint32_t& r3,
                                      uint32_t addr) {
    asm volatile("ldmatrix.sync.aligned.m8n8.x4.shared.b16 {%0,%1,%2,%3}, [%4];"
                 : "=r"(r0), "=r"(r1), "=r"(r2), "=r"(r3) : "r"(addr));
}

__device__ __forceinline__ void mma16816(float* c, const uint32_t* a, uint32_t b0, uint32_t b1) {
    asm volatile(
        "mma.sync.aligned.m16n8k16.row.col.f32.f16.f16.f32 "
        "{%0,%1,%2,%3}, {%4,%5,%6,%7}, {%8,%9}, {%0,%1,%2,%3};"
        : "+f"(c[0]), "+f"(c[1]), "+f"(c[2]), "+f"(c[3])
        : "r"(a[0]), "r"(a[1]), "r"(a[2]), "r"(a[3]), "r"(b0), "r"(b1));
}

__device__ __forceinline__ uint32_t pack2h(float x0, float x1) {
    return ((uint32_t)__half_as_ushort(__float2half_rn(x1)) << 16) |
           (uint32_t)__half_as_ushort(__float2half_rn(x0));
}

__device__ __forceinline__ void store_h2(char* sm, int base, int row, int k,
                                         float x0, float x1) {
    *(uint32_t*)(sm + base + swz(row, k)) = pack2h(x0, x1);
}

__device__ __forceinline__ float silu_f(float z) {
    return __fdividef(z, 1.0f + __expf(-z));
}
__device__ __forceinline__ float emb_f(float tv, float p1, float p2, float d) {
    return tv * (__cosf(d * p1) + __sinf(d * p2));
}

__global__ void __launch_bounds__(NTH, 1)
fused_timestep_mlp_wa2(const float* __restrict__ t,
                       const float* __restrict__ W1,
                       const float* __restrict__ b1,
                       const float* __restrict__ W2,
                       const float* __restrict__ b2,
                       float* __restrict__ out,
                       int n_chunks) {
    extern __shared__ char sm[];
    const uint32_t sb = smem_u32(sm);
    const int tid = threadIdx.x;
    const int wid = tid >> 5;
    const int lane = tid & 31;

    // ---- weight init: fp16 swizzled tiles; biases ----
    for (int e = tid * 4; e < DIM * DIM; e += NTH * 4) {
        const int row = e >> 7, k = e & 127;
        const float4 v1 = *(const float4*)(W1 + e);
        store_h2(sm, OFF_W1, row, k,     v1.x, v1.y);
        store_h2(sm, OFF_W1, row, k + 2, v1.z, v1.w);
        const float4 v2 = *(const float4*)(W2 + e);
        store_h2(sm, OFF_W2, row, k,     v2.x, v2.y);
        store_h2(sm, OFF_W2, row, k + 2, v2.z, v2.w);
    }
    if (tid < 128)      ((float*)(sm + OFF_B1))[tid] = b1[tid];
    else                ((float*)(sm + OFF_B2))[tid - 128] = b2[tid - 128];
    __syncthreads();  // only sync in the kernel

    const float* sB1 = (const float*)(sm + OFF_B1);
    const float* sB2 = (const float*)(sm + OFF_B2);

    // lane geometry
    const int r0 = lane >> 2;                 // frag row (and +8)
    const int kp = (lane & 3) * 2;            // frag col-pair base
    const int g = lane >> 3, i = lane & 7;
    const int wRowLoc = ((g >> 1) << 3) + i;  // B-frag n within 16
    const int wKoff   = (g & 1) << 3;         // B-frag k half

    for (int chunk = blockIdx.x * WARPS + wid; chunk < n_chunks;
         chunk += gridDim.x * WARPS) {
        const int rowBase = chunk * ROWS_PER_WARP;

        // t values for 2 m-tiles x 2 frag rows
        float tv[2][2], p1[2][2], p2[2][2];
#pragma unroll
        for (int mt = 0; mt < 2; ++mt) {
            tv[mt][0] = t[rowBase + mt * 16 + r0];
            tv[mt][1] = t[rowBase + mt * 16 + r0 + 8];
#pragma unroll
            for (int u = 0; u < 2; ++u) {
                p1[mt][u] = tv[mt][u] * (PI_F / 128.0f);
                p2[mt][u] = (1.0f - tv[mt][u]) * (PI_F / 128.0f);
            }
        }

        float acc[2][16][4];
#pragma unroll
        for (int mt = 0; mt < 2; ++mt)
#pragma unroll
            for (int nt = 0; nt < 16; ++nt)
#pragma unroll
                for (int q = 0; q < 4; ++q) acc[mt][nt][q] = 0.0f;

        // ---- GEMM1: A-frags from embedding (MUFU), B = W1 shared by both m-tiles ----
#pragma unroll
        for (int ks = 0; ks < 8; ++ks) {
            const int kb = ks * 16;
            const float dA = (float)(kb + kp), dB = dA + 1.0f;
            const float dC = dA + 8.0f,       dD = dA + 9.0f;
            uint32_t a[2][4];
#pragma unroll
            for (int mt = 0; mt < 2; ++mt) {
                a[mt][0] = pack2h(emb_f(tv[mt][0], p1[mt][0], p2[mt][0], dA),
                                  emb_f(tv[mt][0], p1[mt][0], p2[mt][0], dB));
                a[mt][1] = pack2h(emb_f(tv[mt][1], p1[mt][1], p2[mt][1], dA),
                                  emb_f(tv[mt][1], p1[mt][1], p2[mt][1], dB));
                a[mt][2] = pack2h(emb_f(tv[mt][0], p1[mt][0], p2[mt][0], dC),
                                  emb_f(tv[mt][0], p1[mt][0], p2[mt][0], dD));
                a[mt][3] = pack2h(emb_f(tv[mt][1], p1[mt][1], p2[mt][1], dC),
                                  emb_f(tv[mt][1], p1[mt][1], p2[mt][1], dD));
            }
#pragma unroll
            for (int np = 0; np < 8; ++np) {
                const uint32_t wa = swz(np * 16 + wRowLoc, kb + wKoff);
                uint32_t b[4];
                ldsm4(b[0], b[1], b[2], b[3], sb + OFF_W1 + wa);
#pragma unroll
                for (int mt = 0; mt < 2; ++mt) {
                    mma16816(acc[mt][2 * np],     a[mt], b[0], b[1]);
                    mma16816(acc[mt][2 * np + 1], a[mt], b[2], b[3]);
                }
            }
        }

        // ---- epilogue 1 in registers: bias + silu -> layer-2 A-frags ----
        uint32_t ha[2][8][4];
#pragma unroll
        for (int mt = 0; mt < 2; ++mt) {
#pragma unroll
            for (int ks = 0; ks < 8; ++ks) {
                const float2 bA = *(const float2*)(sB1 + ks * 16 + kp);
                const float2 bB = *(const float2*)(sB1 + ks * 16 + 8 + kp);
                const float* c0 = acc[mt][2 * ks];
                const float* c1 = acc[mt][2 * ks + 1];
                ha[mt][ks][0] = pack2h(silu_f(c0[0] + bA.x), silu_f(c0[1] + bA.y));
                ha[mt][ks][1] = pack2h(silu_f(c0[2] + bA.x), silu_f(c0[3] + bA.y));
                ha[mt][ks][2] = pack2h(silu_f(c1[0] + bB.x), silu_f(c1[1] + bB.y));
                ha[mt][ks][3] = pack2h(silu_f(c1[2] + bB.x), silu_f(c1[3] + bB.y));
            }
        }

        // ---- GEMM2: A = h (registers), B = W2 shared by both m-tiles ----
#pragma unroll
        for (int mt = 0; mt < 2; ++mt)
#pragma unroll
            for (int nt = 0; nt < 16; ++nt)
#pragma unroll
                for (int q = 0; q < 4; ++q) acc[mt][nt][q] = 0.0f;
#pragma unroll
        for (int ks = 0; ks < 8; ++ks) {
            const int kb = ks * 16;
#pragma unroll
            for (int np = 0; np < 8; ++np) {
                const uint32_t wa = swz(np * 16 + wRowLoc, kb + wKoff);
                uint32_t b[4];
                ldsm4(b[0], b[1], b[2], b[3], sb + OFF_W2 + wa);
#pragma unroll
                for (int mt = 0; mt < 2; ++mt) {
                    mma16816(acc[mt][2 * np],     ha[mt][ks], b[0], b[1]);
                    mma16816(acc[mt][2 * np + 1], ha[mt][ks], b[2], b[3]);
                }
            }
        }

        // ---- epilogue 2: bias + silu -> gmem ----
#pragma unroll
        for (int mt = 0; mt < 2; ++mt) {
            float* o0 = out + (size_t)(rowBase + mt * 16 + r0) * DIM;
            float* o1 = out + (size_t)(rowBase + mt * 16 + r0 + 8) * DIM;
#pragma unroll
            for (int nt = 0; nt < 16; ++nt) {
                const int c = nt * 8 + kp;
                const float2 bb = *(const float2*)(sB2 + c);
                const float* a4 = acc[mt][nt];
                *(float2*)(o0 + c) = make_float2(silu_f(a4[0] + bb.x), silu_f(a4[1] + bb.y));
                *(float2*)(o1 + c) = make_float2(silu_f(a4[2] + bb.x), silu_f(a4[3] + bb.y));
            }
        }
    }
}

extern "C" void kernel_launch(void* const* d_in, const int* in_sizes, int n_in,
                              void* d_out, int out_size) {
    const float* t  = (const float*)d_in[0];
    const float* W1 = (const float*)d_in[1];
    const float* b1 = (const float*)d_in[2];
    const float* W2 = (const float*)d_in[3];
    const float* b2 = (const float*)d_in[4];
    float* out = (float*)d_out;

    const int B = in_sizes[0];
    const int n_chunks = B / ROWS_PER_WARP;

    int nsm = 148;
    cudaDeviceGetAttribute(&nsm, cudaDevAttrMultiProcessorCount, 0);

    cudaFuncSetAttribute(fused_timestep_mlp_wa2,
                         cudaFuncAttributeMaxDynamicSharedMemorySize, SMEM_TOTAL);

    fused_timestep_mlp_wa2<<<nsm, NTH, SMEM_TOTAL>>>(t, W1, b1, W2, b2, out, n_chunks);
}